// round 13
// baseline (speedup 1.0000x reference)
#include <cuda_runtime.h>
#include <cuda_bf16.h>
#include <cstdint>

#define DMODEL 1024
#define NHEAD  16
#define DHEAD  64
#define BATCH  4
#define SEQ    2048
#define MTOT   (BATCH * SEQ)          // 8192
#define BH     (BATCH * NHEAD)        // 64

// ---------------------------------------------------------------------------
// Device-global scratch
// ---------------------------------------------------------------------------
__device__ float g_o[MTOT * DMODEL];

__device__ __nv_bfloat16 g_xh[MTOT * DMODEL];
__device__ __nv_bfloat16 g_xl[MTOT * DMODEL];
__device__ __nv_bfloat16 g_oh[MTOT * DMODEL];
__device__ __nv_bfloat16 g_ol[MTOT * DMODEL];
__device__ __nv_bfloat16 g_w1h[3 * DMODEL * DMODEL];
__device__ __nv_bfloat16 g_w1l[3 * DMODEL * DMODEL];
__device__ __nv_bfloat16 g_w2h[DMODEL * DMODEL];
__device__ __nv_bfloat16 g_w2l[DMODEL * DMODEL];

__device__ __nv_bfloat16 g_qh[BH * SEQ * DHEAD];     // [bh][n][d], pre-scaled
__device__ __nv_bfloat16 g_ql[BH * SEQ * DHEAD];
__device__ __nv_bfloat16 g_kh[BH * SEQ * DHEAD];     // [bh][n][d]
__device__ __nv_bfloat16 g_kl[BH * SEQ * DHEAD];
__device__ __nv_bfloat16 g_vth[BH * DHEAD * SEQ];    // [bh][d][n]
__device__ __nv_bfloat16 g_vtl[BH * DHEAD * SEQ];

// ---------------------------------------------------------------------------
// helpers
// ---------------------------------------------------------------------------
__device__ __forceinline__ uint32_t smem_u32(const void* p) {
    uint32_t a;
    asm("{ .reg .u64 t; cvta.to.shared.u64 t, %1; cvt.u32.u64 %0, t; }"
        : "=r"(a) : "l"(p));
    return a;
}

__device__ __forceinline__ void ldsm_x4(uint32_t* r, uint32_t addr) {
    asm volatile("ldmatrix.sync.aligned.m8n8.x4.shared.b16 {%0,%1,%2,%3}, [%4];"
                 : "=r"(r[0]), "=r"(r[1]), "=r"(r[2]), "=r"(r[3]) : "r"(addr));
}

__device__ __forceinline__ void mma_bf16(float* d, const uint32_t* a,
                                         uint32_t b0, uint32_t b1) {
    asm volatile(
        "mma.sync.aligned.m16n8k16.row.col.f32.bf16.bf16.f32 "
        "{%0,%1,%2,%3}, {%4,%5,%6,%7}, {%8,%9}, {%0,%1,%2,%3};"
        : "+f"(d[0]), "+f"(d[1]), "+f"(d[2]), "+f"(d[3])
        : "r"(a[0]), "r"(a[1]), "r"(a[2]), "r"(a[3]), "r"(b0), "r"(b1));
}

__device__ __forceinline__ void split1(float v, __nv_bfloat16& h, __nv_bfloat16& l) {
    h = __float2bfloat16(v);
    l = __float2bfloat16(v - __bfloat162float(h));
}

__device__ __forceinline__ void split2(float a, float b, uint32_t& h, uint32_t& l) {
    __nv_bfloat162 hh;
    hh.x = __float2bfloat16(a);
    hh.y = __float2bfloat16(b);
    float la = a - __bfloat162float(hh.x);
    float lb = b - __bfloat162float(hh.y);
    __nv_bfloat162 ll;
    ll.x = __float2bfloat16(la);
    ll.y = __float2bfloat16(lb);
    h = *(uint32_t*)&hh;
    l = *(uint32_t*)&ll;
}

__device__ __forceinline__ void cp16(uint32_t s, const void* g) {
    asm volatile("cp.async.cg.shared.global [%0], [%1], 16;" :: "r"(s), "l"(g));
}

// ---------------------------------------------------------------------------
// Convert kernels
// ---------------------------------------------------------------------------
__global__ __launch_bounds__(256) void conv_split(const float* __restrict__ in,
                                                  __nv_bfloat16* __restrict__ hi,
                                                  __nv_bfloat16* __restrict__ lo) {
    size_t i4 = (size_t)blockIdx.x * 256 + threadIdx.x;
    float4 v = ((const float4*)in)[i4];
    uint32_t h01, l01, h23, l23;
    split2(v.x, v.y, h01, l01);
    split2(v.z, v.w, h23, l23);
    ((uint2*)hi)[i4] = make_uint2(h01, h23);
    ((uint2*)lo)[i4] = make_uint2(l01, l23);
}

__global__ __launch_bounds__(256) void conv_wT(const float* __restrict__ W,
                                               __nv_bfloat16* __restrict__ Th,
                                               __nv_bfloat16* __restrict__ Tl,
                                               int N) {
    __shared__ float tile[32][33];
    const int tx = threadIdx.x, ty = threadIdx.y;
    const int n = blockIdx.x * 32 + tx;
#pragma unroll
    for (int j = 0; j < 32; j += 8) {
        int k = blockIdx.y * 32 + ty + j;
        tile[ty + j][tx] = W[(size_t)k * N + n];
    }
    __syncthreads();
    const int k = blockIdx.y * 32 + tx;
#pragma unroll
    for (int j = 0; j < 32; j += 8) {
        int n2 = blockIdx.x * 32 + ty + j;
        float v = tile[tx][ty + j];
        __nv_bfloat16 h, l;
        split1(v, h, l);
        Th[(size_t)n2 * DMODEL + k] = h;
        Tl[(size_t)n2 * DMODEL + k] = l;
    }
}

// ---------------------------------------------------------------------------
// HMMA GEMM: CTA 256x128, 8 warps (4M x 2N), warp tile 64x64.
// cp.async double-buffered, BK=64.
// ---------------------------------------------------------------------------
#define BKE    64
#define ROWB   144
#define TILE_A (256 * ROWB)            // 36864
#define TILE_B (128 * ROWB)            // 18432
#define STAGEB (2 * TILE_A + 2 * TILE_B) // 110592
#define SMEM_TOTAL (2 * STAGEB)        // 221184
#define NCHUNK (DMODEL / BKE)          // 16

template <int SCATTER>
__global__ __launch_bounds__(256) void gemm_mma(const __nv_bfloat16* __restrict__ Ah,
                                                const __nv_bfloat16* __restrict__ Al,
                                                const __nv_bfloat16* __restrict__ Bh,
                                                const __nv_bfloat16* __restrict__ Bl,
                                                const float* __restrict__ bias,
                                                float* __restrict__ out) {
    extern __shared__ char smem[];
    const uint32_t sb = smem_u32(smem);

    const int tid  = threadIdx.x;
    const int warp = tid >> 5;
    const int lane = tid & 31;
    const int wm   = warp & 3;         // M group of 64
    const int wn   = warp >> 2;        // N group of 64
    const int n0   = blockIdx.x * 128;
    const int m0   = blockIdx.y * 256;

    float acc[4][8][4];
#pragma unroll
    for (int i = 0; i < 4; i++)
#pragma unroll
        for (int j = 0; j < 8; j++)
#pragma unroll
            for (int r = 0; r < 4; r++) acc[i][j][r] = 0.f;

    const __nv_bfloat16* base0 = Ah + (size_t)m0 * DMODEL;
    const __nv_bfloat16* base1 = Al + (size_t)m0 * DMODEL;
    const __nv_bfloat16* base2 = Bh + (size_t)n0 * DMODEL;
    const __nv_bfloat16* base3 = Bl + (size_t)n0 * DMODEL;

    auto issue = [&](int s, int b) {
        const int k0 = s * BKE;
        const uint32_t dst = sb + b * STAGEB;
#pragma unroll
        for (int i = 0; i < 8; i++) {          // A hi/lo: 256 rows x 8 chunks
            int id = i * 256 + tid;
            int r = id >> 3, c = id & 7;
            cp16(dst + r * ROWB + c * 16,          base0 + (size_t)r * DMODEL + k0 + c * 8);
            cp16(dst + TILE_A + r * ROWB + c * 16, base1 + (size_t)r * DMODEL + k0 + c * 8);
        }
#pragma unroll
        for (int i = 0; i < 4; i++) {          // B hi/lo: 128 rows x 8 chunks
            int id = i * 256 + tid;
            int r = id >> 3, c = id & 7;
            cp16(dst + 2 * TILE_A + r * ROWB + c * 16,          base2 + (size_t)r * DMODEL + k0 + c * 8);
            cp16(dst + 2 * TILE_A + TILE_B + r * ROWB + c * 16, base3 + (size_t)r * DMODEL + k0 + c * 8);
        }
        asm volatile("cp.async.commit_group;");
    };

    issue(0, 0);
    issue(1, 1);

    const int lrow  = lane & 15;
    const int lcol8 = (lane >> 4) * 8;

    for (int s = 0; s < NCHUNK; s++) {
        if (s < NCHUNK - 1)
            asm volatile("cp.async.wait_group 1;" ::: "memory");
        else
            asm volatile("cp.async.wait_group 0;" ::: "memory");
        __syncthreads();

        const uint32_t buf = sb + (s & 1) * STAGEB;
        const uint32_t bAh = buf;
        const uint32_t bAl = buf + TILE_A;
        const uint32_t bBh = buf + 2 * TILE_A;
        const uint32_t bBl = buf + 2 * TILE_A + TILE_B;

#pragma unroll
        for (int ks = 0; ks < 4; ks++) {
            const int kkb = (ks * 16 + lcol8) * 2;
            uint32_t a_hi[4][4], a_lo[4][4], b_cur[4][4];
#pragma unroll
            for (int mf = 0; mf < 4; mf++) {
                int r = wm * 64 + mf * 16 + lrow;
                ldsm_x4(a_hi[mf], bAh + r * ROWB + kkb);
                ldsm_x4(a_lo[mf], bAl + r * ROWB + kkb);
            }
#pragma unroll
            for (int g = 0; g < 4; g++) {
                int r = wn * 64 + g * 16 + lrow;
                ldsm_x4(b_cur[g], bBh + r * ROWB + kkb);
            }
#pragma unroll
            for (int mf = 0; mf < 4; mf++)
#pragma unroll
                for (int j = 0; j < 8; j++) {
                    int g = j >> 1, w = j & 1;
                    mma_bf16(acc[mf][j], a_hi[mf], b_cur[g][w], b_cur[g][w + 2]);
                    mma_bf16(acc[mf][j], a_lo[mf], b_cur[g][w], b_cur[g][w + 2]);
                }
#pragma unroll
            for (int g = 0; g < 4; g++) {
                int r = wn * 64 + g * 16 + lrow;
                ldsm_x4(b_cur[g], bBl + r * ROWB + kkb);
            }
#pragma unroll
            for (int mf = 0; mf < 4; mf++)
#pragma unroll
                for (int j = 0; j < 8; j++) {
                    int g = j >> 1, w = j & 1;
                    mma_bf16(acc[mf][j], a_hi[mf], b_cur[g][w], b_cur[g][w + 2]);
                }
        }
        __syncthreads();
        if (s + 2 < NCHUNK) issue(s + 2, s & 1);
    }

    const int gid = lane >> 2;
    const int tig = lane & 3;
#pragma unroll
    for (int mf = 0; mf < 4; mf++) {
#pragma unroll
        for (int j = 0; j < 8; j++) {
#pragma unroll
            for (int r = 0; r < 4; r++) {
                int m   = m0 + wm * 64 + mf * 16 + gid + ((r >> 1) * 8);
                int col = n0 + wn * 64 + j * 8 + tig * 2 + (r & 1);
                float v = acc[mf][j][r] + bias[col];
                if (SCATTER) {
                    int bi = m >> 11;
                    int ni = m & (SEQ - 1);
                    int which = col >> 10;
                    int rem   = col & 1023;
                    int hd    = rem >> 6;
                    int dd    = rem & 63;
                    int bh    = bi * NHEAD + hd;
                    __nv_bfloat16 h, l;
                    if (which == 0) {
                        split1(v * 0.125f, h, l);
                        size_t idx = ((size_t)bh * SEQ + ni) * DHEAD + dd;
                        g_qh[idx] = h; g_ql[idx] = l;
                    } else if (which == 1) {
                        split1(v, h, l);
                        size_t idx = ((size_t)bh * SEQ + ni) * DHEAD + dd;
                        g_kh[idx] = h; g_kl[idx] = l;
                    } else {
                        split1(v, h, l);
                        size_t idx = ((size_t)bh * DHEAD + dd) * SEQ + ni;
                        g_vth[idx] = h; g_vtl[idx] = l;
                    }
                } else {
                    out[(size_t)m * DMODEL + col] = v;
                }
            }
        }
    }
}

// ---------------------------------------------------------------------------
// HMMA flash attention (causal). CTA = 128 queries x 1 head, 256 thr, 8 warps.
// K/V double-buffered with cp.async prefetch.
// ---------------------------------------------------------------------------
#define AT_ROWB  144
#define AT_QTILE (128 * AT_ROWB)       // 18432
#define AT_KTILE (64 * AT_ROWB)        // 9216
#define AT_KVBUF (4 * AT_KTILE)        // 36864 per buffer (Kh,Kl,Vh,Vl)
#define AT_SSTR  68
#define OFF_QH   0
#define OFF_QL   AT_QTILE
#define OFF_KV   (2 * AT_QTILE)                    // 36864
#define OFF_PH   (OFF_KV + 2 * AT_KVBUF)           // 110592
#define OFF_PL   (OFF_PH + AT_QTILE)               // 129024
#define OFF_S    (OFF_PL + AT_QTILE)               // 147456
#define AT_SMEM  (OFF_S + 128 * AT_SSTR * 4)       // 182272

__global__ __launch_bounds__(256) void attn_mma() {
    extern __shared__ char smem[];
    __shared__ float mrun[128], lrun[128], alph[128];
    const uint32_t sb  = smem_u32(smem);
    const uint32_t sQh = sb + OFF_QH, sQl = sb + OFF_QL;
    const uint32_t sPh = sb + OFF_PH, sPl = sb + OFF_PL;
    float* S = (float*)(smem + OFF_S);

    const int qb   = blockIdx.x;
    const int bh   = blockIdx.y;
    const int tid  = threadIdx.x;
    const int warp = tid >> 5;
    const int lane = tid & 31;
    const int lrow  = lane & 15;
    const int lcol8 = (lane >> 4) * 8;
    const int gid = lane >> 2;
    const int tig = lane & 3;

    // ---- Q hi/lo: 128 rows x 8 chunks each ----
    {
        const __nv_bfloat16* qh = g_qh + ((size_t)bh * SEQ + qb * 128) * DHEAD;
        const __nv_bfloat16* ql = g_ql + ((size_t)bh * SEQ + qb * 128) * DHEAD;
#pragma unroll
        for (int i = 0; i < 4; i++) {
            int id = i * 256 + tid;
            int r = id >> 3, c = id & 7;
            cp16(sQh + r * AT_ROWB + c * 16, qh + (size_t)r * DHEAD + c * 8);
            cp16(sQl + r * AT_ROWB + c * 16, ql + (size_t)r * DHEAD + c * 8);
        }
        asm volatile("cp.async.commit_group;");
    }

    auto load_kv = [&](int kb2, int b) {
        const __nv_bfloat16* kh = g_kh + ((size_t)bh * SEQ + kb2 * 64) * DHEAD;
        const __nv_bfloat16* kl = g_kl + ((size_t)bh * SEQ + kb2 * 64) * DHEAD;
        const __nv_bfloat16* vh = g_vth + (size_t)bh * DHEAD * SEQ + kb2 * 64;
        const __nv_bfloat16* vl = g_vtl + (size_t)bh * DHEAD * SEQ + kb2 * 64;
        const uint32_t d = sb + OFF_KV + b * AT_KVBUF;
#pragma unroll
        for (int i = 0; i < 2; i++) {
            int id = i * 256 + tid;
            int r = id >> 3, c = id & 7;
            cp16(d + r * AT_ROWB + c * 16,                kh + (size_t)r * DHEAD + c * 8);
            cp16(d + AT_KTILE + r * AT_ROWB + c * 16,     kl + (size_t)r * DHEAD + c * 8);
            cp16(d + 2 * AT_KTILE + r * AT_ROWB + c * 16, vh + (size_t)r * SEQ + c * 8);
            cp16(d + 3 * AT_KTILE + r * AT_ROWB + c * 16, vl + (size_t)r * SEQ + c * 8);
        }
        asm volatile("cp.async.commit_group;");
    };

    load_kv(0, 0);

    if (tid < 128) { mrun[tid] = -1e30f; lrun[tid] = 0.f; }

    float o[8][4];
#pragma unroll
    for (int j = 0; j < 8; j++)
#pragma unroll
        for (int r = 0; r < 4; r++) o[j][r] = 0.f;

    const int kbmax = 2 * qb + 1;
    for (int kb = 0; kb <= kbmax; kb++) {
        if (kb < kbmax) load_kv(kb + 1, (kb + 1) & 1);
        if (kb < kbmax)
            asm volatile("cp.async.wait_group 1;" ::: "memory");
        else
            asm volatile("cp.async.wait_group 0;" ::: "memory");
        __syncthreads();

        const uint32_t buf = sb + OFF_KV + (kb & 1) * AT_KVBUF;
        const uint32_t bKh = buf;
        const uint32_t bKl = buf + AT_KTILE;
        const uint32_t bVh = buf + 2 * AT_KTILE;
        const uint32_t bVl = buf + 3 * AT_KTILE;

        // ---- S = Q K^T ----
        float sfr[8][4];
#pragma unroll
        for (int j = 0; j < 8; j++)
#pragma unroll
            for (int r = 0; r < 4; r++) sfr[j][r] = 0.f;

#pragma unroll
        for (int ks = 0; ks < 4; ks++) {
            const int kkb = (ks * 16 + lcol8) * 2;
            uint32_t a_hi[4], a_lo[4], b_cur[4][4];
            int ar = warp * 16 + lrow;
            ldsm_x4(a_hi, sQh + ar * AT_ROWB + kkb);
            ldsm_x4(a_lo, sQl + ar * AT_ROWB + kkb);
#pragma unroll
            for (int g = 0; g < 4; g++)
                ldsm_x4(b_cur[g], bKh + (g * 16 + lrow) * AT_ROWB + kkb);
#pragma unroll
            for (int j = 0; j < 8; j++) {
                int g = j >> 1, w = j & 1;
                mma_bf16(sfr[j], a_hi, b_cur[g][w], b_cur[g][w + 2]);
                mma_bf16(sfr[j], a_lo, b_cur[g][w], b_cur[g][w + 2]);
            }
#pragma unroll
            for (int g = 0; g < 4; g++)
                ldsm_x4(b_cur[g], bKl + (g * 16 + lrow) * AT_ROWB + kkb);
#pragma unroll
            for (int j = 0; j < 8; j++) {
                int g = j >> 1, w = j & 1;
                mma_bf16(sfr[j], a_hi, b_cur[g][w], b_cur[g][w + 2]);
            }
        }
#pragma unroll
        for (int j = 0; j < 8; j++)
#pragma unroll
            for (int r = 0; r < 4; r++) {
                int row = warp * 16 + gid + (r >> 1) * 8;
                int col = j * 8 + tig * 2 + (r & 1);
                S[row * AT_SSTR + col] = sfr[j][r];
            }
        __syncthreads();

        // ---- scalar online softmax: 2 threads per row, 128 rows ----
        {
            const int row   = tid >> 1;
            const int half  = tid & 1;
            const int qglob = qb * 128 + row;
            const int kbase = kb * 64 + half * 32;
            const float* Sr = S + row * AT_SSTR + half * 32;
            float mx = -1e30f;
#pragma unroll
            for (int i = 0; i < 32; i++) {
                float s = (kbase + i <= qglob) ? Sr[i] : -1e30f;
                mx = fmaxf(mx, s);
            }
            mx = fmaxf(mx, __shfl_xor_sync(0xffffffffu, mx, 1));
            float mold = mrun[row];
            float mnew = fmaxf(mold, mx);
            float al   = __expf(mold - mnew);
            __nv_bfloat16* Php = (__nv_bfloat16*)(smem + OFF_PH + row * AT_ROWB) + half * 32;
            __nv_bfloat16* Plp = (__nv_bfloat16*)(smem + OFF_PL + row * AT_ROWB) + half * 32;
            float sum = 0.f;
#pragma unroll
            for (int i = 0; i < 32; i++) {
                float p = (kbase + i <= qglob) ? __expf(Sr[i] - mnew) : 0.f;
                sum += p;
                __nv_bfloat16 h, l;
                split1(p, h, l);
                Php[i] = h; Plp[i] = l;
            }
            sum += __shfl_xor_sync(0xffffffffu, sum, 1);
            if (half == 0) {
                lrun[row] = lrun[row] * al + sum;
                mrun[row] = mnew;
                alph[row] = al;
            }
        }
        __syncthreads();

        // ---- rescale O ----
        {
            float a0 = alph[warp * 16 + gid];
            float a1 = alph[warp * 16 + gid + 8];
#pragma unroll
            for (int j = 0; j < 8; j++) {
                o[j][0] *= a0; o[j][1] *= a0;
                o[j][2] *= a1; o[j][3] *= a1;
            }
        }

        // ---- O += P V ----
#pragma unroll
        for (int ks = 0; ks < 4; ks++) {
            const int kkb = (ks * 16 + lcol8) * 2;
            uint32_t p_hi[4], p_lo[4], b_cur[4][4];
            int ar = warp * 16 + lrow;
            ldsm_x4(p_hi, sPh + ar * AT_ROWB + kkb);
            ldsm_x4(p_lo, sPl + ar * AT_ROWB + kkb);
#pragma unroll
            for (int g = 0; g < 4; g++)
                ldsm_x4(b_cur[g], bVh + (g * 16 + lrow) * AT_ROWB + kkb);
#pragma unroll
            for (int j = 0; j < 8; j++) {
                int g = j >> 1, w = j & 1;
                mma_bf16(o[j], p_hi, b_cur[g][w], b_cur[g][w + 2]);
                mma_bf16(o[j], p_lo, b_cur[g][w], b_cur[g][w + 2]);
            }
#pragma unroll
            for (int g = 0; g < 4; g++)
                ldsm_x4(b_cur[g], bVl + (g * 16 + lrow) * AT_ROWB + kkb);
#pragma unroll
            for (int j = 0; j < 8; j++) {
                int g = j >> 1, w = j & 1;
                mma_bf16(o[j], p_hi, b_cur[g][w], b_cur[g][w + 2]);
            }
        }
        __syncthreads();
    }

    // ---- finalize ----
    {
        float i0 = 1.f / lrun[warp * 16 + gid];
        float i1 = 1.f / lrun[warp * 16 + gid + 8];
        const int bi = bh >> 4;
        const int hd = bh & 15;
#pragma unroll
        for (int j = 0; j < 8; j++)
#pragma unroll
            for (int r = 0; r < 4; r++) {
                int row = qb * 128 + warp * 16 + gid + (r >> 1) * 8;
                int col = j * 8 + tig * 2 + (r & 1);
                float val = o[j][r] * ((r < 2) ? i0 : i1);
                g_o[((size_t)(bi * SEQ + row)) * DMODEL + hd * DHEAD + col] = val;
            }
    }
}

// ---------------------------------------------------------------------------
extern "C" void kernel_launch(void* const* d_in, const int* in_sizes, int n_in,
                              void* d_out, int out_size) {
    const float* x     = (const float*)d_in[0];
    const float* w_qkv = (const float*)d_in[1];
    const float* b_qkv = (const float*)d_in[2];
    const float* w_out = (const float*)d_in[3];
    const float* b_out = (const float*)d_in[4];
    float* out = (float*)d_out;

    __nv_bfloat16 *xh, *xl, *oh, *ol, *w1h, *w1l, *w2h, *w2l;
    float* o;
    cudaGetSymbolAddress((void**)&xh, g_xh);
    cudaGetSymbolAddress((void**)&xl, g_xl);
    cudaGetSymbolAddress((void**)&oh, g_oh);
    cudaGetSymbolAddress((void**)&ol, g_ol);
    cudaGetSymbolAddress((void**)&w1h, g_w1h);
    cudaGetSymbolAddress((void**)&w1l, g_w1l);
    cudaGetSymbolAddress((void**)&w2h, g_w2h);
    cudaGetSymbolAddress((void**)&w2l, g_w2l);
    cudaGetSymbolAddress((void**)&o, g_o);

    cudaFuncSetAttribute(gemm_mma<1>, cudaFuncAttributeMaxDynamicSharedMemorySize, SMEM_TOTAL);
    cudaFuncSetAttribute(gemm_mma<0>, cudaFuncAttributeMaxDynamicSharedMemorySize, SMEM_TOTAL);
    cudaFuncSetAttribute(attn_mma,    cudaFuncAttributeMaxDynamicSharedMemorySize, AT_SMEM);

    conv_split<<<MTOT * DMODEL / 4 / 256, 256>>>(x, xh, xl);
    conv_wT<<<dim3(3 * DMODEL / 32, DMODEL / 32), dim3(32, 8)>>>(w_qkv, w1h, w1l, 3 * DMODEL);
    conv_wT<<<dim3(DMODEL / 32, DMODEL / 32), dim3(32, 8)>>>(w_out, w2h, w2l, DMODEL);

    gemm_mma<1><<<dim3(3 * DMODEL / 128, MTOT / 256), 256, SMEM_TOTAL>>>(
        xh, xl, w1h, w1l, b_qkv, nullptr);

    attn_mma<<<dim3(SEQ / 128, BH), 256, AT_SMEM>>>();

    conv_split<<<MTOT * DMODEL / 4 / 256, 256>>>(o, oh, ol);

    gemm_mma<0><<<dim3(DMODEL / 128, MTOT / 256), 256, SMEM_TOTAL>>>(
        oh, ol, w2h, w2l, b_out, out);
}

// round 14
// speedup vs baseline: 1.3875x; 1.3875x over previous
#include <cuda_runtime.h>
#include <cuda_bf16.h>
#include <cstdint>

#define DMODEL 1024
#define NHEAD  16
#define DHEAD  64
#define BATCH  4
#define SEQ    2048
#define MTOT   (BATCH * SEQ)          // 8192
#define BH     (BATCH * NHEAD)        // 64

// ---------------------------------------------------------------------------
// Device-global scratch
// ---------------------------------------------------------------------------
__device__ float g_o[MTOT * DMODEL];

__device__ __nv_bfloat16 g_xh[MTOT * DMODEL];
__device__ __nv_bfloat16 g_xl[MTOT * DMODEL];
__device__ __nv_bfloat16 g_oh[MTOT * DMODEL];
__device__ __nv_bfloat16 g_ol[MTOT * DMODEL];
__device__ __nv_bfloat16 g_w1h[3 * DMODEL * DMODEL];
__device__ __nv_bfloat16 g_w1l[3 * DMODEL * DMODEL];
__device__ __nv_bfloat16 g_w2h[DMODEL * DMODEL];
__device__ __nv_bfloat16 g_w2l[DMODEL * DMODEL];

__device__ __nv_bfloat16 g_qh[BH * SEQ * DHEAD];     // [bh][n][d], pre-scaled
__device__ __nv_bfloat16 g_ql[BH * SEQ * DHEAD];
__device__ __nv_bfloat16 g_kh[BH * SEQ * DHEAD];     // [bh][n][d]
__device__ __nv_bfloat16 g_kl[BH * SEQ * DHEAD];
__device__ __nv_bfloat16 g_vth[BH * DHEAD * SEQ];    // [bh][d][n]
__device__ __nv_bfloat16 g_vtl[BH * DHEAD * SEQ];

// ---------------------------------------------------------------------------
// helpers
// ---------------------------------------------------------------------------
__device__ __forceinline__ uint32_t smem_u32(const void* p) {
    uint32_t a;
    asm("{ .reg .u64 t; cvta.to.shared.u64 t, %1; cvt.u32.u64 %0, t; }"
        : "=r"(a) : "l"(p));
    return a;
}

__device__ __forceinline__ void ldsm_x4(uint32_t* r, uint32_t addr) {
    asm volatile("ldmatrix.sync.aligned.m8n8.x4.shared.b16 {%0,%1,%2,%3}, [%4];"
                 : "=r"(r[0]), "=r"(r[1]), "=r"(r[2]), "=r"(r[3]) : "r"(addr));
}

__device__ __forceinline__ void mma_bf16(float* d, const uint32_t* a,
                                         uint32_t b0, uint32_t b1) {
    asm volatile(
        "mma.sync.aligned.m16n8k16.row.col.f32.bf16.bf16.f32 "
        "{%0,%1,%2,%3}, {%4,%5,%6,%7}, {%8,%9}, {%0,%1,%2,%3};"
        : "+f"(d[0]), "+f"(d[1]), "+f"(d[2]), "+f"(d[3])
        : "r"(a[0]), "r"(a[1]), "r"(a[2]), "r"(a[3]), "r"(b0), "r"(b1));
}

__device__ __forceinline__ void split1(float v, __nv_bfloat16& h, __nv_bfloat16& l) {
    h = __float2bfloat16(v);
    l = __float2bfloat16(v - __bfloat162float(h));
}

__device__ __forceinline__ void split2(float a, float b, uint32_t& h, uint32_t& l) {
    __nv_bfloat162 hh;
    hh.x = __float2bfloat16(a);
    hh.y = __float2bfloat16(b);
    float la = a - __bfloat162float(hh.x);
    float lb = b - __bfloat162float(hh.y);
    __nv_bfloat162 ll;
    ll.x = __float2bfloat16(la);
    ll.y = __float2bfloat16(lb);
    h = *(uint32_t*)&hh;
    l = *(uint32_t*)&ll;
}

__device__ __forceinline__ void cp16(uint32_t s, const void* g) {
    asm volatile("cp.async.cg.shared.global [%0], [%1], 16;" :: "r"(s), "l"(g));
}

// ---------------------------------------------------------------------------
// Convert kernels
// ---------------------------------------------------------------------------
__global__ __launch_bounds__(256) void conv_split(const float* __restrict__ in,
                                                  __nv_bfloat16* __restrict__ hi,
                                                  __nv_bfloat16* __restrict__ lo) {
    size_t i4 = (size_t)blockIdx.x * 256 + threadIdx.x;
    float4 v = ((const float4*)in)[i4];
    uint32_t h01, l01, h23, l23;
    split2(v.x, v.y, h01, l01);
    split2(v.z, v.w, h23, l23);
    ((uint2*)hi)[i4] = make_uint2(h01, h23);
    ((uint2*)lo)[i4] = make_uint2(l01, l23);
}

__global__ __launch_bounds__(256) void conv_wT(const float* __restrict__ W,
                                               __nv_bfloat16* __restrict__ Th,
                                               __nv_bfloat16* __restrict__ Tl,
                                               int N) {
    __shared__ float tile[32][33];
    const int tx = threadIdx.x, ty = threadIdx.y;
    const int n = blockIdx.x * 32 + tx;
#pragma unroll
    for (int j = 0; j < 32; j += 8) {
        int k = blockIdx.y * 32 + ty + j;
        tile[ty + j][tx] = W[(size_t)k * N + n];
    }
    __syncthreads();
    const int k = blockIdx.y * 32 + tx;
#pragma unroll
    for (int j = 0; j < 32; j += 8) {
        int n2 = blockIdx.x * 32 + ty + j;
        float v = tile[tx][ty + j];
        __nv_bfloat16 h, l;
        split1(v, h, l);
        Th[(size_t)n2 * DMODEL + k] = h;
        Tl[(size_t)n2 * DMODEL + k] = l;
    }
}

// ---------------------------------------------------------------------------
// HMMA GEMM (reverted to R10-measured config): CTA 128x128, 8 warps (4M x 2N),
// warp tile 32x64, cp.async double-buffered, BK=64.
// ---------------------------------------------------------------------------
#define BKE    64
#define ROWB   144
#define TILEB  (128 * ROWB)              // 18432
#define STAGEB (4 * TILEB)               // 73728
#define SMEM_TOTAL (2 * STAGEB)          // 147456
#define NCHUNK (DMODEL / BKE)            // 16

template <int SCATTER>
__global__ __launch_bounds__(256) void gemm_mma(const __nv_bfloat16* __restrict__ Ah,
                                                const __nv_bfloat16* __restrict__ Al,
                                                const __nv_bfloat16* __restrict__ Bh,
                                                const __nv_bfloat16* __restrict__ Bl,
                                                const float* __restrict__ bias,
                                                float* __restrict__ out) {
    extern __shared__ char smem[];
    const uint32_t sb = smem_u32(smem);

    const int tid  = threadIdx.x;
    const int warp = tid >> 5;
    const int lane = tid & 31;
    const int wm   = warp & 3;
    const int wn   = warp >> 2;
    const int n0   = blockIdx.x * 128;
    const int m0   = blockIdx.y * 128;

    float acc[2][8][4];
#pragma unroll
    for (int i = 0; i < 2; i++)
#pragma unroll
        for (int j = 0; j < 8; j++)
#pragma unroll
            for (int r = 0; r < 4; r++) acc[i][j][r] = 0.f;

    const __nv_bfloat16* base0 = Ah + (size_t)m0 * DMODEL;
    const __nv_bfloat16* base1 = Al + (size_t)m0 * DMODEL;
    const __nv_bfloat16* base2 = Bh + (size_t)n0 * DMODEL;
    const __nv_bfloat16* base3 = Bl + (size_t)n0 * DMODEL;

    const int cr = tid >> 3;
    const int cc = tid & 7;

    auto issue = [&](int s, int b) {
        const int k0 = s * BKE;
        const uint32_t dst = sb + b * STAGEB;
#pragma unroll
        for (int it = 0; it < 16; it++) {
            const int tile = it >> 2;
            const int r    = (it & 3) * 32 + cr;
            const __nv_bfloat16* src;
            if (tile == 0)      src = base0 + (size_t)r * DMODEL + k0 + cc * 8;
            else if (tile == 1) src = base1 + (size_t)r * DMODEL + k0 + cc * 8;
            else if (tile == 2) src = base2 + (size_t)r * DMODEL + k0 + cc * 8;
            else                src = base3 + (size_t)r * DMODEL + k0 + cc * 8;
            cp16(dst + tile * TILEB + r * ROWB + cc * 16, src);
        }
        asm volatile("cp.async.commit_group;");
    };

    issue(0, 0);
    issue(1, 1);

    const int lrow  = lane & 15;
    const int lcol8 = (lane >> 4) * 8;

    for (int s = 0; s < NCHUNK; s++) {
        if (s < NCHUNK - 1)
            asm volatile("cp.async.wait_group 1;" ::: "memory");
        else
            asm volatile("cp.async.wait_group 0;" ::: "memory");
        __syncthreads();

        const uint32_t buf = sb + (s & 1) * STAGEB;
        const uint32_t bAh = buf;
        const uint32_t bAl = buf + TILEB;
        const uint32_t bBh = buf + 2 * TILEB;
        const uint32_t bBl = buf + 3 * TILEB;

#pragma unroll
        for (int ks = 0; ks < 4; ks++) {
            const int kkb = (ks * 16 + lcol8) * 2;
            uint32_t a_hi[2][4], a_lo[2][4], b_cur[4][4];
#pragma unroll
            for (int mf = 0; mf < 2; mf++) {
                int r = wm * 32 + mf * 16 + lrow;
                ldsm_x4(a_hi[mf], bAh + r * ROWB + kkb);
                ldsm_x4(a_lo[mf], bAl + r * ROWB + kkb);
            }
#pragma unroll
            for (int g = 0; g < 4; g++) {
                int r = wn * 64 + g * 16 + lrow;
                ldsm_x4(b_cur[g], bBh + r * ROWB + kkb);
            }
#pragma unroll
            for (int mf = 0; mf < 2; mf++)
#pragma unroll
                for (int j = 0; j < 8; j++) {
                    int g = j >> 1, w = j & 1;
                    mma_bf16(acc[mf][j], a_hi[mf], b_cur[g][w], b_cur[g][w + 2]);
                    mma_bf16(acc[mf][j], a_lo[mf], b_cur[g][w], b_cur[g][w + 2]);
                }
#pragma unroll
            for (int g = 0; g < 4; g++) {
                int r = wn * 64 + g * 16 + lrow;
                ldsm_x4(b_cur[g], bBl + r * ROWB + kkb);
            }
#pragma unroll
            for (int mf = 0; mf < 2; mf++)
#pragma unroll
                for (int j = 0; j < 8; j++) {
                    int g = j >> 1, w = j & 1;
                    mma_bf16(acc[mf][j], a_hi[mf], b_cur[g][w], b_cur[g][w + 2]);
                }
        }
        __syncthreads();
        if (s + 2 < NCHUNK) issue(s + 2, s & 1);
    }

    const int gid = lane >> 2;
    const int tig = lane & 3;
#pragma unroll
    for (int mf = 0; mf < 2; mf++) {
#pragma unroll
        for (int j = 0; j < 8; j++) {
#pragma unroll
            for (int r = 0; r < 4; r++) {
                int m   = m0 + wm * 32 + mf * 16 + gid + ((r >> 1) * 8);
                int col = n0 + wn * 64 + j * 8 + tig * 2 + (r & 1);
                float v = acc[mf][j][r] + bias[col];
                if (SCATTER) {
                    int bi = m >> 11;
                    int ni = m & (SEQ - 1);
                    int which = col >> 10;
                    int rem   = col & 1023;
                    int hd    = rem >> 6;
                    int dd    = rem & 63;
                    int bh    = bi * NHEAD + hd;
                    __nv_bfloat16 h, l;
                    if (which == 0) {
                        split1(v * 0.125f, h, l);
                        size_t idx = ((size_t)bh * SEQ + ni) * DHEAD + dd;
                        g_qh[idx] = h; g_ql[idx] = l;
                    } else if (which == 1) {
                        split1(v, h, l);
                        size_t idx = ((size_t)bh * SEQ + ni) * DHEAD + dd;
                        g_kh[idx] = h; g_kl[idx] = l;
                    } else {
                        split1(v, h, l);
                        size_t idx = ((size_t)bh * DHEAD + dd) * SEQ + ni;
                        g_vth[idx] = h; g_vtl[idx] = l;
                    }
                } else {
                    out[(size_t)m * DMODEL + col] = v;
                }
            }
        }
    }
}

// ---------------------------------------------------------------------------
// HMMA flash attention, register-resident softmax (FA2-style).
// CTA = 128 queries x 1 head, 256 thr, 8 warps (warp w: rows w*16..w*16+15).
// S C-fragments repack directly as P A-fragments; no S/P SMEM round trip.
// ---------------------------------------------------------------------------
#define AT_ROWB  144
#define AT_QTILE (128 * AT_ROWB)       // 18432
#define AT_KTILE (64 * AT_ROWB)        // 9216
#define AT_KVBUF (4 * AT_KTILE)        // 36864 (Kh,Kl,Vh,Vl)
#define OFF_KV   (2 * AT_QTILE)        // 36864
#define AT_SMEM  (OFF_KV + 2 * AT_KVBUF)  // 110592

__global__ __launch_bounds__(256) void attn_mma() {
    extern __shared__ char smem[];
    const uint32_t sb  = smem_u32(smem);
    const uint32_t sQh = sb, sQl = sb + AT_QTILE;

    const int qb   = blockIdx.x;
    const int bh   = blockIdx.y;
    const int tid  = threadIdx.x;
    const int warp = tid >> 5;
    const int lane = tid & 31;
    const int lrow  = lane & 15;
    const int lcol8 = (lane >> 4) * 8;
    const int gid = lane >> 2;
    const int tig = lane & 3;

    // ---- Q hi/lo ----
    {
        const __nv_bfloat16* qh = g_qh + ((size_t)bh * SEQ + qb * 128) * DHEAD;
        const __nv_bfloat16* ql = g_ql + ((size_t)bh * SEQ + qb * 128) * DHEAD;
#pragma unroll
        for (int i = 0; i < 4; i++) {
            int id = i * 256 + tid;
            int r = id >> 3, c = id & 7;
            cp16(sQh + r * AT_ROWB + c * 16, qh + (size_t)r * DHEAD + c * 8);
            cp16(sQl + r * AT_ROWB + c * 16, ql + (size_t)r * DHEAD + c * 8);
        }
        asm volatile("cp.async.commit_group;");
    }

    auto load_kv = [&](int kb2, int b) {
        const __nv_bfloat16* kh = g_kh + ((size_t)bh * SEQ + kb2 * 64) * DHEAD;
        const __nv_bfloat16* kl = g_kl + ((size_t)bh * SEQ + kb2 * 64) * DHEAD;
        const __nv_bfloat16* vh = g_vth + (size_t)bh * DHEAD * SEQ + kb2 * 64;
        const __nv_bfloat16* vl = g_vtl + (size_t)bh * DHEAD * SEQ + kb2 * 64;
        const uint32_t d = sb + OFF_KV + b * AT_KVBUF;
#pragma unroll
        for (int i = 0; i < 2; i++) {
            int id = i * 256 + tid;
            int r = id >> 3, c = id & 7;
            cp16(d + r * AT_ROWB + c * 16,                kh + (size_t)r * DHEAD + c * 8);
            cp16(d + AT_KTILE + r * AT_ROWB + c * 16,     kl + (size_t)r * DHEAD + c * 8);
            cp16(d + 2 * AT_KTILE + r * AT_ROWB + c * 16, vh + (size_t)r * SEQ + c * 8);
            cp16(d + 3 * AT_KTILE + r * AT_ROWB + c * 16, vl + (size_t)r * SEQ + c * 8);
        }
        asm volatile("cp.async.commit_group;");
    };

    load_kv(0, 0);

    // per-thread softmax state for rows (gid) and (gid+8) of this warp's 16
    float m_0 = -1e30f, m_1 = -1e30f, l_0 = 0.f, l_1 = 0.f;
    const int row0 = qb * 128 + warp * 16 + gid;
    const int row1 = row0 + 8;

    float o[8][4];
#pragma unroll
    for (int j = 0; j < 8; j++)
#pragma unroll
        for (int r = 0; r < 4; r++) o[j][r] = 0.f;

    const int kbmax = 2 * qb + 1;
    for (int kb = 0; kb <= kbmax; kb++) {
        if (kb > 0) __syncthreads();             // prev compute done before overwrite
        if (kb < kbmax) load_kv(kb + 1, (kb + 1) & 1);
        if (kb < kbmax)
            asm volatile("cp.async.wait_group 1;" ::: "memory");
        else
            asm volatile("cp.async.wait_group 0;" ::: "memory");
        __syncthreads();

        const uint32_t buf = sb + OFF_KV + (kb & 1) * AT_KVBUF;
        const uint32_t bKh = buf;
        const uint32_t bKl = buf + AT_KTILE;
        const uint32_t bVh = buf + 2 * AT_KTILE;
        const uint32_t bVl = buf + 3 * AT_KTILE;

        // ---- S = Q K^T (3-pass hi/lo) ----
        float sfr[8][4];
#pragma unroll
        for (int j = 0; j < 8; j++)
#pragma unroll
            for (int r = 0; r < 4; r++) sfr[j][r] = 0.f;

#pragma unroll
        for (int ks = 0; ks < 4; ks++) {
            const int kkb = (ks * 16 + lcol8) * 2;
            uint32_t a_hi[4], a_lo[4], b_cur[4][4];
            int ar = warp * 16 + lrow;
            ldsm_x4(a_hi, sQh + ar * AT_ROWB + kkb);
            ldsm_x4(a_lo, sQl + ar * AT_ROWB + kkb);
#pragma unroll
            for (int g = 0; g < 4; g++)
                ldsm_x4(b_cur[g], bKh + (g * 16 + lrow) * AT_ROWB + kkb);
#pragma unroll
            for (int j = 0; j < 8; j++) {
                int g = j >> 1, w = j & 1;
                mma_bf16(sfr[j], a_hi, b_cur[g][w], b_cur[g][w + 2]);
                mma_bf16(sfr[j], a_lo, b_cur[g][w], b_cur[g][w + 2]);
            }
#pragma unroll
            for (int g = 0; g < 4; g++)
                ldsm_x4(b_cur[g], bKl + (g * 16 + lrow) * AT_ROWB + kkb);
#pragma unroll
            for (int j = 0; j < 8; j++) {
                int g = j >> 1, w = j & 1;
                mma_bf16(sfr[j], a_hi, b_cur[g][w], b_cur[g][w + 2]);
            }
        }

        // ---- causal mask in-register (only near the diagonal) ----
        if (kb * 64 + 63 > row0) {
#pragma unroll
            for (int j = 0; j < 8; j++)
#pragma unroll
                for (int r = 0; r < 4; r++) {
                    int col = kb * 64 + j * 8 + tig * 2 + (r & 1);
                    int rw  = (r < 2) ? row0 : row1;
                    if (col > rw) sfr[j][r] = -1e30f;
                }
        }

        // ---- register online softmax: rows gid / gid+8, quad reduction ----
        float mx0 = -1e30f, mx1 = -1e30f;
#pragma unroll
        for (int j = 0; j < 8; j++) {
            mx0 = fmaxf(mx0, fmaxf(sfr[j][0], sfr[j][1]));
            mx1 = fmaxf(mx1, fmaxf(sfr[j][2], sfr[j][3]));
        }
        mx0 = fmaxf(mx0, __shfl_xor_sync(0xffffffffu, mx0, 1));
        mx0 = fmaxf(mx0, __shfl_xor_sync(0xffffffffu, mx0, 2));
        mx1 = fmaxf(mx1, __shfl_xor_sync(0xffffffffu, mx1, 1));
        mx1 = fmaxf(mx1, __shfl_xor_sync(0xffffffffu, mx1, 2));

        float mn0 = fmaxf(m_0, mx0), mn1 = fmaxf(m_1, mx1);
        float al0 = __expf(m_0 - mn0), al1 = __expf(m_1 - mn1);
        m_0 = mn0; m_1 = mn1;

        float s0 = 0.f, s1 = 0.f;
#pragma unroll
        for (int j = 0; j < 8; j++) {
            sfr[j][0] = __expf(sfr[j][0] - mn0);
            sfr[j][1] = __expf(sfr[j][1] - mn0);
            sfr[j][2] = __expf(sfr[j][2] - mn1);
            sfr[j][3] = __expf(sfr[j][3] - mn1);
            s0 += sfr[j][0] + sfr[j][1];
            s1 += sfr[j][2] + sfr[j][3];
        }
        s0 += __shfl_xor_sync(0xffffffffu, s0, 1);
        s0 += __shfl_xor_sync(0xffffffffu, s0, 2);
        s1 += __shfl_xor_sync(0xffffffffu, s1, 1);
        s1 += __shfl_xor_sync(0xffffffffu, s1, 2);
        l_0 = l_0 * al0 + s0;
        l_1 = l_1 * al1 + s1;

        // ---- rescale O ----
#pragma unroll
        for (int j = 0; j < 8; j++) {
            o[j][0] *= al0; o[j][1] *= al0;
            o[j][2] *= al1; o[j][3] *= al1;
        }

        // ---- O += P V : repack S C-frags as P A-frags, 3-pass hi/lo ----
#pragma unroll
        for (int kp = 0; kp < 4; kp++) {
            uint32_t ph[4], pl[4];
            split2(sfr[2 * kp][0],     sfr[2 * kp][1],     ph[0], pl[0]);
            split2(sfr[2 * kp][2],     sfr[2 * kp][3],     ph[1], pl[1]);
            split2(sfr[2 * kp + 1][0], sfr[2 * kp + 1][1], ph[2], pl[2]);
            split2(sfr[2 * kp + 1][2], sfr[2 * kp + 1][3], ph[3], pl[3]);

            const int kkb = (kp * 16 + lcol8) * 2;
            uint32_t b_cur[4][4];
#pragma unroll
            for (int g = 0; g < 4; g++)
                ldsm_x4(b_cur[g], bVh + (g * 16 + lrow) * AT_ROWB + kkb);
#pragma unroll
            for (int j = 0; j < 8; j++) {
                int g = j >> 1, w = j & 1;
                mma_bf16(o[j], ph, b_cur[g][w], b_cur[g][w + 2]);
                mma_bf16(o[j], pl, b_cur[g][w], b_cur[g][w + 2]);
            }
#pragma unroll
            for (int g = 0; g < 4; g++)
                ldsm_x4(b_cur[g], bVl + (g * 16 + lrow) * AT_ROWB + kkb);
#pragma unroll
            for (int j = 0; j < 8; j++) {
                int g = j >> 1, w = j & 1;
                mma_bf16(o[j], ph, b_cur[g][w], b_cur[g][w + 2]);
            }
        }
    }

    // ---- finalize ----
    {
        float i0 = 1.f / l_0;
        float i1 = 1.f / l_1;
        const int bi = bh >> 4;
        const int hd = bh & 15;
#pragma unroll
        for (int j = 0; j < 8; j++)
#pragma unroll
            for (int r = 0; r < 4; r++) {
                int row = (r < 2) ? row0 : row1;
                int col = j * 8 + tig * 2 + (r & 1);
                float val = o[j][r] * ((r < 2) ? i0 : i1);
                g_o[((size_t)(bi * SEQ + row)) * DMODEL + hd * DHEAD + col] = val;
            }
    }
}

// ---------------------------------------------------------------------------
extern "C" void kernel_launch(void* const* d_in, const int* in_sizes, int n_in,
                              void* d_out, int out_size) {
    const float* x     = (const float*)d_in[0];
    const float* w_qkv = (const float*)d_in[1];
    const float* b_qkv = (const float*)d_in[2];
    const float* w_out = (const float*)d_in[3];
    const float* b_out = (const float*)d_in[4];
    float* out = (float*)d_out;

    __nv_bfloat16 *xh, *xl, *oh, *ol, *w1h, *w1l, *w2h, *w2l;
    float* o;
    cudaGetSymbolAddress((void**)&xh, g_xh);
    cudaGetSymbolAddress((void**)&xl, g_xl);
    cudaGetSymbolAddress((void**)&oh, g_oh);
    cudaGetSymbolAddress((void**)&ol, g_ol);
    cudaGetSymbolAddress((void**)&w1h, g_w1h);
    cudaGetSymbolAddress((void**)&w1l, g_w1l);
    cudaGetSymbolAddress((void**)&w2h, g_w2h);
    cudaGetSymbolAddress((void**)&w2l, g_w2l);
    cudaGetSymbolAddress((void**)&o, g_o);

    cudaFuncSetAttribute(gemm_mma<1>, cudaFuncAttributeMaxDynamicSharedMemorySize, SMEM_TOTAL);
    cudaFuncSetAttribute(gemm_mma<0>, cudaFuncAttributeMaxDynamicSharedMemorySize, SMEM_TOTAL);
    cudaFuncSetAttribute(attn_mma,    cudaFuncAttributeMaxDynamicSharedMemorySize, AT_SMEM);

    conv_split<<<MTOT * DMODEL / 4 / 256, 256>>>(x, xh, xl);
    conv_wT<<<dim3(3 * DMODEL / 32, DMODEL / 32), dim3(32, 8)>>>(w_qkv, w1h, w1l, 3 * DMODEL);
    conv_wT<<<dim3(DMODEL / 32, DMODEL / 32), dim3(32, 8)>>>(w_out, w2h, w2l, DMODEL);

    gemm_mma<1><<<dim3(3 * DMODEL / 128, MTOT / 128), 256, SMEM_TOTAL>>>(
        xh, xl, w1h, w1l, b_qkv, nullptr);

    attn_mma<<<dim3(SEQ / 128, BH), 256, AT_SMEM>>>();

    conv_split<<<MTOT * DMODEL / 4 / 256, 256>>>(o, oh, ol);

    gemm_mma<0><<<dim3(DMODEL / 128, MTOT / 128), 256, SMEM_TOTAL>>>(
        oh, ol, w2h, w2l, b_out, out);
}

// round 15
// speedup vs baseline: 1.4365x; 1.0353x over previous
#include <cuda_runtime.h>
#include <cuda_bf16.h>
#include <cstdint>

#define DMODEL 1024
#define NHEAD  16
#define DHEAD  64
#define BATCH  4
#define SEQ    2048
#define MTOT   (BATCH * SEQ)          // 8192
#define BH     (BATCH * NHEAD)        // 64

// ---------------------------------------------------------------------------
// Device-global scratch
// ---------------------------------------------------------------------------
__device__ float g_o[MTOT * DMODEL];

__device__ __nv_bfloat16 g_xh[MTOT * DMODEL];
__device__ __nv_bfloat16 g_xl[MTOT * DMODEL];
__device__ __nv_bfloat16 g_oh[MTOT * DMODEL];
__device__ __nv_bfloat16 g_ol[MTOT * DMODEL];
__device__ __nv_bfloat16 g_w1h[3 * DMODEL * DMODEL];
__device__ __nv_bfloat16 g_w1l[3 * DMODEL * DMODEL];
__device__ __nv_bfloat16 g_w2h[DMODEL * DMODEL];
__device__ __nv_bfloat16 g_w2l[DMODEL * DMODEL];

__device__ __nv_bfloat16 g_qh[BH * SEQ * DHEAD];     // [bh][n][d], pre-scaled
__device__ __nv_bfloat16 g_ql[BH * SEQ * DHEAD];
__device__ __nv_bfloat16 g_kh[BH * SEQ * DHEAD];     // [bh][n][d]
__device__ __nv_bfloat16 g_kl[BH * SEQ * DHEAD];
__device__ __nv_bfloat16 g_vth[BH * DHEAD * SEQ];    // [bh][d][n]
__device__ __nv_bfloat16 g_vtl[BH * DHEAD * SEQ];

// ---------------------------------------------------------------------------
// helpers
// ---------------------------------------------------------------------------
__device__ __forceinline__ uint32_t smem_u32(const void* p) {
    uint32_t a;
    asm("{ .reg .u64 t; cvta.to.shared.u64 t, %1; cvt.u32.u64 %0, t; }"
        : "=r"(a) : "l"(p));
    return a;
}

__device__ __forceinline__ void ldsm_x4(uint32_t* r, uint32_t addr) {
    asm volatile("ldmatrix.sync.aligned.m8n8.x4.shared.b16 {%0,%1,%2,%3}, [%4];"
                 : "=r"(r[0]), "=r"(r[1]), "=r"(r[2]), "=r"(r[3]) : "r"(addr));
}

__device__ __forceinline__ void mma_bf16(float* d, const uint32_t* a,
                                         uint32_t b0, uint32_t b1) {
    asm volatile(
        "mma.sync.aligned.m16n8k16.row.col.f32.bf16.bf16.f32 "
        "{%0,%1,%2,%3}, {%4,%5,%6,%7}, {%8,%9}, {%0,%1,%2,%3};"
        : "+f"(d[0]), "+f"(d[1]), "+f"(d[2]), "+f"(d[3])
        : "r"(a[0]), "r"(a[1]), "r"(a[2]), "r"(a[3]), "r"(b0), "r"(b1));
}

__device__ __forceinline__ void split1(float v, __nv_bfloat16& h, __nv_bfloat16& l) {
    h = __float2bfloat16(v);
    l = __float2bfloat16(v - __bfloat162float(h));
}

__device__ __forceinline__ void split2(float a, float b, uint32_t& h, uint32_t& l) {
    __nv_bfloat162 hh;
    hh.x = __float2bfloat16(a);
    hh.y = __float2bfloat16(b);
    float la = a - __bfloat162float(hh.x);
    float lb = b - __bfloat162float(hh.y);
    __nv_bfloat162 ll;
    ll.x = __float2bfloat16(la);
    ll.y = __float2bfloat16(lb);
    h = *(uint32_t*)&hh;
    l = *(uint32_t*)&ll;
}

__device__ __forceinline__ void cp16(uint32_t s, const void* g) {
    asm volatile("cp.async.cg.shared.global [%0], [%1], 16;" :: "r"(s), "l"(g));
}

// ---------------------------------------------------------------------------
// Convert kernels
// ---------------------------------------------------------------------------
__global__ __launch_bounds__(256) void conv_split(const float* __restrict__ in,
                                                  __nv_bfloat16* __restrict__ hi,
                                                  __nv_bfloat16* __restrict__ lo) {
    size_t i4 = (size_t)blockIdx.x * 256 + threadIdx.x;
    float4 v = ((const float4*)in)[i4];
    uint32_t h01, l01, h23, l23;
    split2(v.x, v.y, h01, l01);
    split2(v.z, v.w, h23, l23);
    ((uint2*)hi)[i4] = make_uint2(h01, h23);
    ((uint2*)lo)[i4] = make_uint2(l01, l23);
}

__global__ __launch_bounds__(256) void conv_wT(const float* __restrict__ W,
                                               __nv_bfloat16* __restrict__ Th,
                                               __nv_bfloat16* __restrict__ Tl,
                                               int N) {
    __shared__ float tile[32][33];
    const int tx = threadIdx.x, ty = threadIdx.y;
    const int n = blockIdx.x * 32 + tx;
#pragma unroll
    for (int j = 0; j < 32; j += 8) {
        int k = blockIdx.y * 32 + ty + j;
        tile[ty + j][tx] = W[(size_t)k * N + n];
    }
    __syncthreads();
    const int k = blockIdx.y * 32 + tx;
#pragma unroll
    for (int j = 0; j < 32; j += 8) {
        int n2 = blockIdx.x * 32 + ty + j;
        float v = tile[tx][ty + j];
        __nv_bfloat16 h, l;
        split1(v, h, l);
        Th[(size_t)n2 * DMODEL + k] = h;
        Tl[(size_t)n2 * DMODEL + k] = l;
    }
}

// ---------------------------------------------------------------------------
// HMMA GEMM: CTA 128x128, 8 warps (4M x 2N), warp tile 32x64.
// BK=32, small stages so 2 CTAs fit per SM (80KB SMEM/CTA).
// ---------------------------------------------------------------------------
#define BKE    32
#define ROWB   80                        // 64B data + 16B pad (conflict-free)
#define TILEB  (128 * ROWB)              // 10240
#define STAGEB (4 * TILEB)               // 40960
#define SMEM_TOTAL (2 * STAGEB)          // 81920 -> 2 CTAs/SM
#define NCHUNK (DMODEL / BKE)            // 32

template <int SCATTER>
__global__ __launch_bounds__(256) void gemm_mma(const __nv_bfloat16* __restrict__ Ah,
                                                const __nv_bfloat16* __restrict__ Al,
                                                const __nv_bfloat16* __restrict__ Bh,
                                                const __nv_bfloat16* __restrict__ Bl,
                                                const float* __restrict__ bias,
                                                float* __restrict__ out) {
    extern __shared__ char smem[];
    const uint32_t sb = smem_u32(smem);

    const int tid  = threadIdx.x;
    const int warp = tid >> 5;
    const int lane = tid & 31;
    const int wm   = warp & 3;
    const int wn   = warp >> 2;
    const int n0   = blockIdx.x * 128;
    const int m0   = blockIdx.y * 128;

    float acc[2][8][4];
#pragma unroll
    for (int i = 0; i < 2; i++)
#pragma unroll
        for (int j = 0; j < 8; j++)
#pragma unroll
            for (int r = 0; r < 4; r++) acc[i][j][r] = 0.f;

    const __nv_bfloat16* base0 = Ah + (size_t)m0 * DMODEL;
    const __nv_bfloat16* base1 = Al + (size_t)m0 * DMODEL;
    const __nv_bfloat16* base2 = Bh + (size_t)n0 * DMODEL;
    const __nv_bfloat16* base3 = Bl + (size_t)n0 * DMODEL;

    const int cr = tid >> 2;             // 0..63 (row pair base)
    const int cc = tid & 3;              // 0..3  (16B chunk in 64B row)

    auto issue = [&](int s, int b) {
        const int k0 = s * BKE;
        const uint32_t dst = sb + b * STAGEB;
#pragma unroll
        for (int it = 0; it < 8; it++) {
            const int tile = it >> 1;
            const int r    = (it & 1) * 64 + cr;
            const __nv_bfloat16* src;
            if (tile == 0)      src = base0 + (size_t)r * DMODEL + k0 + cc * 8;
            else if (tile == 1) src = base1 + (size_t)r * DMODEL + k0 + cc * 8;
            else if (tile == 2) src = base2 + (size_t)r * DMODEL + k0 + cc * 8;
            else                src = base3 + (size_t)r * DMODEL + k0 + cc * 8;
            cp16(dst + tile * TILEB + r * ROWB + cc * 16, src);
        }
        asm volatile("cp.async.commit_group;");
    };

    issue(0, 0);
    issue(1, 1);

    const int lrow  = lane & 15;
    const int lcol8 = (lane >> 4) * 8;

    for (int s = 0; s < NCHUNK; s++) {
        if (s < NCHUNK - 1)
            asm volatile("cp.async.wait_group 1;" ::: "memory");
        else
            asm volatile("cp.async.wait_group 0;" ::: "memory");
        __syncthreads();

        const uint32_t buf = sb + (s & 1) * STAGEB;
        const uint32_t bAh = buf;
        const uint32_t bAl = buf + TILEB;
        const uint32_t bBh = buf + 2 * TILEB;
        const uint32_t bBl = buf + 3 * TILEB;

#pragma unroll
        for (int ks = 0; ks < 2; ks++) {
            const int kkb = (ks * 16 + lcol8) * 2;
            uint32_t a_hi[2][4], a_lo[2][4], b_cur[4][4];
#pragma unroll
            for (int mf = 0; mf < 2; mf++) {
                int r = wm * 32 + mf * 16 + lrow;
                ldsm_x4(a_hi[mf], bAh + r * ROWB + kkb);
                ldsm_x4(a_lo[mf], bAl + r * ROWB + kkb);
            }
#pragma unroll
            for (int g = 0; g < 4; g++) {
                int r = wn * 64 + g * 16 + lrow;
                ldsm_x4(b_cur[g], bBh + r * ROWB + kkb);
            }
#pragma unroll
            for (int mf = 0; mf < 2; mf++)
#pragma unroll
                for (int j = 0; j < 8; j++) {
                    int g = j >> 1, w = j & 1;
                    mma_bf16(acc[mf][j], a_hi[mf], b_cur[g][w], b_cur[g][w + 2]);
                    mma_bf16(acc[mf][j], a_lo[mf], b_cur[g][w], b_cur[g][w + 2]);
                }
#pragma unroll
            for (int g = 0; g < 4; g++) {
                int r = wn * 64 + g * 16 + lrow;
                ldsm_x4(b_cur[g], bBl + r * ROWB + kkb);
            }
#pragma unroll
            for (int mf = 0; mf < 2; mf++)
#pragma unroll
                for (int j = 0; j < 8; j++) {
                    int g = j >> 1, w = j & 1;
                    mma_bf16(acc[mf][j], a_hi[mf], b_cur[g][w], b_cur[g][w + 2]);
                }
        }
        __syncthreads();
        if (s + 2 < NCHUNK) issue(s + 2, s & 1);
    }

    const int gid = lane >> 2;
    const int tig = lane & 3;
#pragma unroll
    for (int mf = 0; mf < 2; mf++) {
#pragma unroll
        for (int j = 0; j < 8; j++) {
#pragma unroll
            for (int r = 0; r < 4; r++) {
                int m   = m0 + wm * 32 + mf * 16 + gid + ((r >> 1) * 8);
                int col = n0 + wn * 64 + j * 8 + tig * 2 + (r & 1);
                float v = acc[mf][j][r] + bias[col];
                if (SCATTER) {
                    int bi = m >> 11;
                    int ni = m & (SEQ - 1);
                    int which = col >> 10;
                    int rem   = col & 1023;
                    int hd    = rem >> 6;
                    int dd    = rem & 63;
                    int bh    = bi * NHEAD + hd;
                    __nv_bfloat16 h, l;
                    if (which == 0) {
                        split1(v * 0.125f, h, l);
                        size_t idx = ((size_t)bh * SEQ + ni) * DHEAD + dd;
                        g_qh[idx] = h; g_ql[idx] = l;
                    } else if (which == 1) {
                        split1(v, h, l);
                        size_t idx = ((size_t)bh * SEQ + ni) * DHEAD + dd;
                        g_kh[idx] = h; g_kl[idx] = l;
                    } else {
                        split1(v, h, l);
                        size_t idx = ((size_t)bh * DHEAD + dd) * SEQ + ni;
                        g_vth[idx] = h; g_vtl[idx] = l;
                    }
                } else {
                    out[(size_t)m * DMODEL + col] = v;
                }
            }
        }
    }
}

// ---------------------------------------------------------------------------
// HMMA flash attention, register-resident softmax (unchanged from R14 winner).
// ---------------------------------------------------------------------------
#define AT_ROWB  144
#define AT_QTILE (128 * AT_ROWB)       // 18432
#define AT_KTILE (64 * AT_ROWB)        // 9216
#define AT_KVBUF (4 * AT_KTILE)        // 36864 (Kh,Kl,Vh,Vl)
#define OFF_KV   (2 * AT_QTILE)        // 36864
#define AT_SMEM  (OFF_KV + 2 * AT_KVBUF)  // 110592

__global__ __launch_bounds__(256) void attn_mma() {
    extern __shared__ char smem[];
    const uint32_t sb  = smem_u32(smem);
    const uint32_t sQh = sb, sQl = sb + AT_QTILE;

    const int qb   = blockIdx.x;
    const int bh   = blockIdx.y;
    const int tid  = threadIdx.x;
    const int warp = tid >> 5;
    const int lane = tid & 31;
    const int lrow  = lane & 15;
    const int lcol8 = (lane >> 4) * 8;
    const int gid = lane >> 2;
    const int tig = lane & 3;

    // ---- Q hi/lo ----
    {
        const __nv_bfloat16* qh = g_qh + ((size_t)bh * SEQ + qb * 128) * DHEAD;
        const __nv_bfloat16* ql = g_ql + ((size_t)bh * SEQ + qb * 128) * DHEAD;
#pragma unroll
        for (int i = 0; i < 4; i++) {
            int id = i * 256 + tid;
            int r = id >> 3, c = id & 7;
            cp16(sQh + r * AT_ROWB + c * 16, qh + (size_t)r * DHEAD + c * 8);
            cp16(sQl + r * AT_ROWB + c * 16, ql + (size_t)r * DHEAD + c * 8);
        }
        asm volatile("cp.async.commit_group;");
    }

    auto load_kv = [&](int kb2, int b) {
        const __nv_bfloat16* kh = g_kh + ((size_t)bh * SEQ + kb2 * 64) * DHEAD;
        const __nv_bfloat16* kl = g_kl + ((size_t)bh * SEQ + kb2 * 64) * DHEAD;
        const __nv_bfloat16* vh = g_vth + (size_t)bh * DHEAD * SEQ + kb2 * 64;
        const __nv_bfloat16* vl = g_vtl + (size_t)bh * DHEAD * SEQ + kb2 * 64;
        const uint32_t d = sb + OFF_KV + b * AT_KVBUF;
#pragma unroll
        for (int i = 0; i < 2; i++) {
            int id = i * 256 + tid;
            int r = id >> 3, c = id & 7;
            cp16(d + r * AT_ROWB + c * 16,                kh + (size_t)r * DHEAD + c * 8);
            cp16(d + AT_KTILE + r * AT_ROWB + c * 16,     kl + (size_t)r * DHEAD + c * 8);
            cp16(d + 2 * AT_KTILE + r * AT_ROWB + c * 16, vh + (size_t)r * SEQ + c * 8);
            cp16(d + 3 * AT_KTILE + r * AT_ROWB + c * 16, vl + (size_t)r * SEQ + c * 8);
        }
        asm volatile("cp.async.commit_group;");
    };

    load_kv(0, 0);

    float m_0 = -1e30f, m_1 = -1e30f, l_0 = 0.f, l_1 = 0.f;
    const int row0 = qb * 128 + warp * 16 + gid;
    const int row1 = row0 + 8;

    float o[8][4];
#pragma unroll
    for (int j = 0; j < 8; j++)
#pragma unroll
        for (int r = 0; r < 4; r++) o[j][r] = 0.f;

    const int kbmax = 2 * qb + 1;
    for (int kb = 0; kb <= kbmax; kb++) {
        if (kb > 0) __syncthreads();
        if (kb < kbmax) load_kv(kb + 1, (kb + 1) & 1);
        if (kb < kbmax)
            asm volatile("cp.async.wait_group 1;" ::: "memory");
        else
            asm volatile("cp.async.wait_group 0;" ::: "memory");
        __syncthreads();

        const uint32_t buf = sb + OFF_KV + (kb & 1) * AT_KVBUF;
        const uint32_t bKh = buf;
        const uint32_t bKl = buf + AT_KTILE;
        const uint32_t bVh = buf + 2 * AT_KTILE;
        const uint32_t bVl = buf + 3 * AT_KTILE;

        // ---- S = Q K^T (3-pass hi/lo) ----
        float sfr[8][4];
#pragma unroll
        for (int j = 0; j < 8; j++)
#pragma unroll
            for (int r = 0; r < 4; r++) sfr[j][r] = 0.f;

#pragma unroll
        for (int ks = 0; ks < 4; ks++) {
            const int kkb = (ks * 16 + lcol8) * 2;
            uint32_t a_hi[4], a_lo[4], b_cur[4][4];
            int ar = warp * 16 + lrow;
            ldsm_x4(a_hi, sQh + ar * AT_ROWB + kkb);
            ldsm_x4(a_lo, sQl + ar * AT_ROWB + kkb);
#pragma unroll
            for (int g = 0; g < 4; g++)
                ldsm_x4(b_cur[g], bKh + (g * 16 + lrow) * AT_ROWB + kkb);
#pragma unroll
            for (int j = 0; j < 8; j++) {
                int g = j >> 1, w = j & 1;
                mma_bf16(sfr[j], a_hi, b_cur[g][w], b_cur[g][w + 2]);
                mma_bf16(sfr[j], a_lo, b_cur[g][w], b_cur[g][w + 2]);
            }
#pragma unroll
            for (int g = 0; g < 4; g++)
                ldsm_x4(b_cur[g], bKl + (g * 16 + lrow) * AT_ROWB + kkb);
#pragma unroll
            for (int j = 0; j < 8; j++) {
                int g = j >> 1, w = j & 1;
                mma_bf16(sfr[j], a_hi, b_cur[g][w], b_cur[g][w + 2]);
            }
        }

        // ---- causal mask in-register ----
        if (kb * 64 + 63 > row0) {
#pragma unroll
            for (int j = 0; j < 8; j++)
#pragma unroll
                for (int r = 0; r < 4; r++) {
                    int col = kb * 64 + j * 8 + tig * 2 + (r & 1);
                    int rw  = (r < 2) ? row0 : row1;
                    if (col > rw) sfr[j][r] = -1e30f;
                }
        }

        // ---- register online softmax ----
        float mx0 = -1e30f, mx1 = -1e30f;
#pragma unroll
        for (int j = 0; j < 8; j++) {
            mx0 = fmaxf(mx0, fmaxf(sfr[j][0], sfr[j][1]));
            mx1 = fmaxf(mx1, fmaxf(sfr[j][2], sfr[j][3]));
        }
        mx0 = fmaxf(mx0, __shfl_xor_sync(0xffffffffu, mx0, 1));
        mx0 = fmaxf(mx0, __shfl_xor_sync(0xffffffffu, mx0, 2));
        mx1 = fmaxf(mx1, __shfl_xor_sync(0xffffffffu, mx1, 1));
        mx1 = fmaxf(mx1, __shfl_xor_sync(0xffffffffu, mx1, 2));

        float mn0 = fmaxf(m_0, mx0), mn1 = fmaxf(m_1, mx1);
        float al0 = __expf(m_0 - mn0), al1 = __expf(m_1 - mn1);
        m_0 = mn0; m_1 = mn1;

        float s0 = 0.f, s1 = 0.f;
#pragma unroll
        for (int j = 0; j < 8; j++) {
            sfr[j][0] = __expf(sfr[j][0] - mn0);
            sfr[j][1] = __expf(sfr[j][1] - mn0);
            sfr[j][2] = __expf(sfr[j][2] - mn1);
            sfr[j][3] = __expf(sfr[j][3] - mn1);
            s0 += sfr[j][0] + sfr[j][1];
            s1 += sfr[j][2] + sfr[j][3];
        }
        s0 += __shfl_xor_sync(0xffffffffu, s0, 1);
        s0 += __shfl_xor_sync(0xffffffffu, s0, 2);
        s1 += __shfl_xor_sync(0xffffffffu, s1, 1);
        s1 += __shfl_xor_sync(0xffffffffu, s1, 2);
        l_0 = l_0 * al0 + s0;
        l_1 = l_1 * al1 + s1;

#pragma unroll
        for (int j = 0; j < 8; j++) {
            o[j][0] *= al0; o[j][1] *= al0;
            o[j][2] *= al1; o[j][3] *= al1;
        }

        // ---- O += P V : repack S C-frags as P A-frags ----
#pragma unroll
        for (int kp = 0; kp < 4; kp++) {
            uint32_t ph[4], pl[4];
            split2(sfr[2 * kp][0],     sfr[2 * kp][1],     ph[0], pl[0]);
            split2(sfr[2 * kp][2],     sfr[2 * kp][3],     ph[1], pl[1]);
            split2(sfr[2 * kp + 1][0], sfr[2 * kp + 1][1], ph[2], pl[2]);
            split2(sfr[2 * kp + 1][2], sfr[2 * kp + 1][3], ph[3], pl[3]);

            const int kkb = (kp * 16 + lcol8) * 2;
            uint32_t b_cur[4][4];
#pragma unroll
            for (int g = 0; g < 4; g++)
                ldsm_x4(b_cur[g], bVh + (g * 16 + lrow) * AT_ROWB + kkb);
#pragma unroll
            for (int j = 0; j < 8; j++) {
                int g = j >> 1, w = j & 1;
                mma_bf16(o[j], ph, b_cur[g][w], b_cur[g][w + 2]);
                mma_bf16(o[j], pl, b_cur[g][w], b_cur[g][w + 2]);
            }
#pragma unroll
            for (int g = 0; g < 4; g++)
                ldsm_x4(b_cur[g], bVl + (g * 16 + lrow) * AT_ROWB + kkb);
#pragma unroll
            for (int j = 0; j < 8; j++) {
                int g = j >> 1, w = j & 1;
                mma_bf16(o[j], ph, b_cur[g][w], b_cur[g][w + 2]);
            }
        }
    }

    // ---- finalize ----
    {
        float i0 = 1.f / l_0;
        float i1 = 1.f / l_1;
        const int bi = bh >> 4;
        const int hd = bh & 15;
#pragma unroll
        for (int j = 0; j < 8; j++)
#pragma unroll
            for (int r = 0; r < 4; r++) {
                int row = (r < 2) ? row0 : row1;
                int col = j * 8 + tig * 2 + (r & 1);
                float val = o[j][r] * ((r < 2) ? i0 : i1);
                g_o[((size_t)(bi * SEQ + row)) * DMODEL + hd * DHEAD + col] = val;
            }
    }
}

// ---------------------------------------------------------------------------
extern "C" void kernel_launch(void* const* d_in, const int* in_sizes, int n_in,
                              void* d_out, int out_size) {
    const float* x     = (const float*)d_in[0];
    const float* w_qkv = (const float*)d_in[1];
    const float* b_qkv = (const float*)d_in[2];
    const float* w_out = (const float*)d_in[3];
    const float* b_out = (const float*)d_in[4];
    float* out = (float*)d_out;

    __nv_bfloat16 *xh, *xl, *oh, *ol, *w1h, *w1l, *w2h, *w2l;
    float* o;
    cudaGetSymbolAddress((void**)&xh, g_xh);
    cudaGetSymbolAddress((void**)&xl, g_xl);
    cudaGetSymbolAddress((void**)&oh, g_oh);
    cudaGetSymbolAddress((void**)&ol, g_ol);
    cudaGetSymbolAddress((void**)&w1h, g_w1h);
    cudaGetSymbolAddress((void**)&w1l, g_w1l);
    cudaGetSymbolAddress((void**)&w2h, g_w2h);
    cudaGetSymbolAddress((void**)&w2l, g_w2l);
    cudaGetSymbolAddress((void**)&o, g_o);

    cudaFuncSetAttribute(gemm_mma<1>, cudaFuncAttributeMaxDynamicSharedMemorySize, SMEM_TOTAL);
    cudaFuncSetAttribute(gemm_mma<0>, cudaFuncAttributeMaxDynamicSharedMemorySize, SMEM_TOTAL);
    cudaFuncSetAttribute(attn_mma,    cudaFuncAttributeMaxDynamicSharedMemorySize, AT_SMEM);

    conv_split<<<MTOT * DMODEL / 4 / 256, 256>>>(x, xh, xl);
    conv_wT<<<dim3(3 * DMODEL / 32, DMODEL / 32), dim3(32, 8)>>>(w_qkv, w1h, w1l, 3 * DMODEL);
    conv_wT<<<dim3(DMODEL / 32, DMODEL / 32), dim3(32, 8)>>>(w_out, w2h, w2l, DMODEL);

    gemm_mma<1><<<dim3(3 * DMODEL / 128, MTOT / 128), 256, SMEM_TOTAL>>>(
        xh, xl, w1h, w1l, b_qkv, nullptr);

    attn_mma<<<dim3(SEQ / 128, BH), 256, AT_SMEM>>>();

    conv_split<<<MTOT * DMODEL / 4 / 256, 256>>>(o, oh, ol);

    gemm_mma<0><<<dim3(DMODEL / 128, MTOT / 128), 256, SMEM_TOTAL>>>(
        oh, ol, w2h, w2l, b_out, out);
}